// round 8
// baseline (speedup 1.0000x reference)
#include <cuda_runtime.h>
#include <cuda_bf16.h>
#include <cstdint>

// Scratch (static device memory — no cudaMalloc anywhere)
__device__ float g_q [4096u * 1024u];   // Q  = x @ w_q       [4096,1024]
__device__ float g_kv[4096u * 2048u];   // KV = x @ w_vk      [4096,2048]
__device__ float g_ao[4096u * 1024u];   // attention output   [4096,1024]

// ---------------------------------------------------------------------------
// helpers
// ---------------------------------------------------------------------------
__device__ __forceinline__ uint32_t f2tf32(float f) {
    uint32_t u;
    asm("cvt.rna.tf32.f32 %0, %1;" : "=r"(u) : "f"(f));
    return u;
}
__device__ __forceinline__ void tf32_split(float x, uint32_t& hi, uint32_t& lo) {
    hi = f2tf32(x);
    lo = f2tf32(x - __uint_as_float(hi));
}
__device__ __forceinline__ void mma_tf32(float c[4], const uint32_t a[4], const uint32_t b[2]) {
    asm volatile(
        "mma.sync.aligned.m16n8k8.row.col.f32.tf32.tf32.f32 "
        "{%0,%1,%2,%3}, {%4,%5,%6,%7}, {%8,%9}, {%0,%1,%2,%3};\n"
        : "+f"(c[0]), "+f"(c[1]), "+f"(c[2]), "+f"(c[3])
        : "r"(a[0]), "r"(a[1]), "r"(a[2]), "r"(a[3]), "r"(b[0]), "r"(b[1]));
}
__device__ __forceinline__ void mma3(float c[4], const uint32_t ah[4], const uint32_t al[4],
                                     const uint32_t bh[2], const uint32_t bl[2]) {
    mma_tf32(c, ah, bl);
    mma_tf32(c, al, bh);
    mma_tf32(c, ah, bh);
}
__device__ __forceinline__ uint32_t smem_u32(const void* p) {
    return (uint32_t)__cvta_generic_to_shared(p);
}
__device__ __forceinline__ void cp16(uint32_t saddr, const void* gptr) {
    asm volatile("cp.async.cg.shared.global [%0], [%1], 16;\n" :: "r"(saddr), "l"(gptr));
}
#define CP_COMMIT() asm volatile("cp.async.commit_group;\n" ::: "memory")
#define CP_WAIT1()  asm volatile("cp.async.wait_group 1;\n" ::: "memory")

// ---------------------------------------------------------------------------
// 3xTF32 GEMM with cp.async double-buffered raw staging, split-at-read.
// C[M,N]=A[M,K]@B[K,N] row-major fp32. Block 128x128, BK=32, 256 thr (8 warps).
// ---------------------------------------------------------------------------
#define GA (128 * 36)
#define GB (32 * 136)
#define GSTAGE (GA + GB)
#define GEMM_SMEM (2 * GSTAGE * 4)

__global__ void __launch_bounds__(256, 2)
gemm_3xtf32_kernel(const float* __restrict__ A, const float* __restrict__ B,
                   float* __restrict__ C, int M, int N, int K) {
    extern __shared__ float smf[];
    const uint32_t sbase = smem_u32(smf);

    const int tid  = threadIdx.x;
    const int lane = tid & 31;
    const int warp = tid >> 5;
    const int g = lane >> 2;
    const int t = lane & 3;
    const int wm = warp >> 2;
    const int wn = warp & 3;
    const int bm = blockIdx.y * 128;
    const int bn = blockIdx.x * 128;

    const int ar = tid >> 3;          // 0..31
    const int ac = (tid & 7) << 2;    // 0..28
    const int br = tid >> 5;          // 0..7
    const int bc = lane << 2;         // 0..124

    float acc[4][4][4];
#pragma unroll
    for (int i = 0; i < 4; i++)
#pragma unroll
        for (int j = 0; j < 4; j++)
#pragma unroll
            for (int v = 0; v < 4; v++) acc[i][j][v] = 0.f;

    // issue cp.async for one k-stage
    auto load_stage = [&](int k0, int s) {
        uint32_t abase = sbase + (uint32_t)(s * GSTAGE) * 4u;
        uint32_t bbase = abase + (uint32_t)GA * 4u;
#pragma unroll
        for (int p = 0; p < 4; p++) {
            int r = ar + p * 32;
            cp16(abase + (uint32_t)(r * 36 + ac) * 4u,
                 A + (size_t)(bm + r) * K + k0 + ac);
        }
#pragma unroll
        for (int p = 0; p < 4; p++) {
            int r = br + p * 8;
            cp16(bbase + (uint32_t)(r * 136 + bc) * 4u,
                 B + (size_t)(k0 + r) * N + bn + bc);
        }
    };

    const int nk = K / 32;
    load_stage(0, 0);  CP_COMMIT();
    load_stage(32, 1); CP_COMMIT();
    CP_WAIT1();
    __syncthreads();

    for (int i = 0; i < nk; i++) {
        const float* Ar = smf + (i & 1) * GSTAGE;
        const float* Br = Ar + GA;

        // ---- compute from raw stage (split at read) ----
#pragma unroll
        for (int ks = 0; ks < 4; ks++) {
            const int kb = ks * 8;
            uint32_t afh[4][4], afl[4][4], bfh[4][2], bfl[4][2];
#pragma unroll
            for (int mt = 0; mt < 4; mt++) {
                int r0 = wm * 64 + mt * 16;
                int i0 = (r0 + g) * 36 + kb + t;
                int i1 = (r0 + 8 + g) * 36 + kb + t;
                tf32_split(Ar[i0],     afh[mt][0], afl[mt][0]);
                tf32_split(Ar[i1],     afh[mt][1], afl[mt][1]);
                tf32_split(Ar[i0 + 4], afh[mt][2], afl[mt][2]);
                tf32_split(Ar[i1 + 4], afh[mt][3], afl[mt][3]);
            }
#pragma unroll
            for (int nt = 0; nt < 4; nt++) {
                int c0 = wn * 32 + nt * 8;
                int i0 = (kb + t) * 136 + c0 + g;
                int i1 = (kb + t + 4) * 136 + c0 + g;
                tf32_split(Br[i0], bfh[nt][0], bfl[nt][0]);
                tf32_split(Br[i1], bfh[nt][1], bfl[nt][1]);
            }
#pragma unroll
            for (int mt = 0; mt < 4; mt++)
#pragma unroll
                for (int nt = 0; nt < 4; nt++)
                    mma3(acc[mt][nt], afh[mt], afl[mt], bfh[nt], bfl[nt]);
        }
        __syncthreads();                       // stage (i&1) fully consumed
        if (i + 2 < nk) load_stage((i + 2) * 32, i & 1);
        CP_COMMIT();
        CP_WAIT1();                            // stage for tile i+1 complete
        __syncthreads();
    }

#pragma unroll
    for (int mt = 0; mt < 4; mt++) {
        int row = bm + wm * 64 + mt * 16 + g;
#pragma unroll
        for (int nt = 0; nt < 4; nt++) {
            int col = bn + wn * 32 + nt * 8 + 2 * t;
            *reinterpret_cast<float2*>(C + (size_t)row * N + col) =
                make_float2(acc[mt][nt][0], acc[mt][nt][1]);
            *reinterpret_cast<float2*>(C + (size_t)(row + 8) * N + col) =
                make_float2(acc[mt][nt][2], acc[mt][nt][3]);
        }
    }
}

// ---------------------------------------------------------------------------
// 3xTF32 flash attention, 256 threads (8 warps), 128 q-rows per block.
// cp.async double-buffered raw K/V staging; split staging pass raw->hi/lo smem.
// NOTE: reference MULTIPLIES logits by sqrt(64)=8.
// smem: raw K/V x2 stages (8*FT) + Kh/Kl/Vh/Vl (4*FT... wait laid out below)
//   [0,4*FT)      raw stages: s*(2*FT) + {K:0, V:FT}
//   [4*FT,8*FT)   Kh, Kl, Vh, Vl (FT each)
//   [8*FT, 8*FT+2*PT)  Ph, Pl (PT each; also raw-Q staging in Ph)
// FT=64*68, PT=128*68. Total = (8*4352 + 2*8704)*4 = 208896 bytes.
// ---------------------------------------------------------------------------
#define FT (64 * 68)
#define PT (128 * 68)
#define FLASH_SMEM ((8 * FT + 2 * PT) * 4)

__global__ void __launch_bounds__(256, 1)
flash_3xtf32_kernel(const float* __restrict__ Q, const float* __restrict__ KV,
                    float* __restrict__ O) {
    extern __shared__ float smf[];
    const uint32_t sbase = smem_u32(smf);
    uint32_t* Kh = reinterpret_cast<uint32_t*>(smf + 4 * FT);
    uint32_t* Kl = Kh + FT;
    uint32_t* Vh = Kh + 2 * FT;
    uint32_t* Vl = Kh + 3 * FT;
    uint32_t* Ph = reinterpret_cast<uint32_t*>(smf + 8 * FT);
    uint32_t* Pl = Ph + PT;

    const int tid  = threadIdx.x;
    const int lane = tid & 31;
    const int warp = tid >> 5;
    const int g = lane >> 2;
    const int t = lane & 3;
    const int wr = warp * 16;               // warp's q-row base (0..112)

    const int b  = blockIdx.z;
    const int h  = blockIdx.y;
    const int q0 = blockIdx.x * 128;

    const float* Kb = KV + (size_t)b * 2048 * 2048 + h * 64;

    // issue cp.async for KV tile (64 rows) into raw stage s
    auto load_stage = [&](int j0, int s) {
        uint32_t kbase = sbase + (uint32_t)(s * 2 * FT) * 4u;
        uint32_t vbase = kbase + (uint32_t)FT * 4u;
#pragma unroll
        for (int p = 0; p < 4; p++) {
            int idx = tid + p * 256;
            int r = idx >> 4;
            int c = (idx & 15) << 2;
            const float* kp = Kb + (size_t)(j0 + r) * 2048 + c;
            cp16(kbase + (uint32_t)(r * 68 + c) * 4u, kp);
            cp16(vbase + (uint32_t)(r * 68 + c) * 4u, kp + 1024);
        }
    };

    // prologue: start K/V tile 0,1 loads, then stage Q while they fly
    load_stage(0, 0);  CP_COMMIT();
    load_stage(64, 1); CP_COMMIT();

    float* Phf = reinterpret_cast<float*>(Ph);
#pragma unroll
    for (int p = 0; p < 8; p++) {
        int idx = tid + p * 256;            // 0..2047 = 128 rows x 16 float4
        int r = idx >> 4;
        int c = (idx & 15) << 2;
        *reinterpret_cast<float4*>(Phf + r * 68 + c) =
            *reinterpret_cast<const float4*>(
                Q + (size_t)(b * 2048 + q0 + r) * 1024 + h * 64 + c);
    }
    __syncthreads();

    uint32_t qh[8][4], ql[8][4];
#pragma unroll
    for (int ks = 0; ks < 8; ks++) {
        int kb = ks * 8;
        tf32_split(Phf[(wr + g) * 68 + kb + t],         qh[ks][0], ql[ks][0]);
        tf32_split(Phf[(wr + 8 + g) * 68 + kb + t],     qh[ks][1], ql[ks][1]);
        tf32_split(Phf[(wr + g) * 68 + kb + t + 4],     qh[ks][2], ql[ks][2]);
        tf32_split(Phf[(wr + 8 + g) * 68 + kb + t + 4], qh[ks][3], ql[ks][3]);
    }
    __syncthreads();          // Ph free for P staging
    CP_WAIT1();
    __syncthreads();          // raw stage 0 visible to all

    float of[8][4];
#pragma unroll
    for (int i = 0; i < 8; i++)
#pragma unroll
        for (int v = 0; v < 4; v++) of[i][v] = 0.f;
    float m0 = -1e30f, m1 = -1e30f, l0 = 0.f, l1 = 0.f;

    for (int it = 0; it < 32; it++) {
        const int s = it & 1;
        const float* Kraw = smf + s * 2 * FT;
        const float* Vraw = Kraw + FT;

        // ---- split staging: raw -> hi/lo ----
#pragma unroll
        for (int p = 0; p < 4; p++) {
            int idx = tid + p * 256;
            int r = idx >> 4;
            int c = (idx & 15) << 2;
            float4 k4 = *reinterpret_cast<const float4*>(Kraw + r * 68 + c);
            uint4 hh, ll;
            tf32_split(k4.x, hh.x, ll.x); tf32_split(k4.y, hh.y, ll.y);
            tf32_split(k4.z, hh.z, ll.z); tf32_split(k4.w, hh.w, ll.w);
            *reinterpret_cast<uint4*>(&Kh[r * 68 + c]) = hh;
            *reinterpret_cast<uint4*>(&Kl[r * 68 + c]) = ll;
            float4 v4 = *reinterpret_cast<const float4*>(Vraw + r * 68 + c);
            tf32_split(v4.x, hh.x, ll.x); tf32_split(v4.y, hh.y, ll.y);
            tf32_split(v4.z, hh.z, ll.z); tf32_split(v4.w, hh.w, ll.w);
            *reinterpret_cast<uint4*>(&Vh[r * 68 + c]) = hh;
            *reinterpret_cast<uint4*>(&Vl[r * 68 + c]) = ll;
        }
        __syncthreads();      // hi/lo visible; raw stage s consumed

        // prefetch tile it+2 into the stage we just freed
        if (it + 2 < 32) load_stage((it + 2) * 64, s);
        CP_COMMIT();

        // ---- S = Q K^T (3xTF32) ----
        float sf[8][4];
#pragma unroll
        for (int nt = 0; nt < 8; nt++)
#pragma unroll
            for (int v = 0; v < 4; v++) sf[nt][v] = 0.f;
#pragma unroll
        for (int ks = 0; ks < 8; ks++) {
            int kb = ks * 8;
#pragma unroll
            for (int nt = 0; nt < 8; nt++) {
                int i0 = (nt * 8 + g) * 68 + kb + t;
                uint32_t bh[2] = { Kh[i0], Kh[i0 + 4] };
                uint32_t bl[2] = { Kl[i0], Kl[i0 + 4] };
                mma3(sf[nt], qh[ks], ql[ks], bh, bl);
            }
        }

        // ---- online softmax (x8 scale; rows g and g+8) ----
        float r0m = -1e30f, r1m = -1e30f;
#pragma unroll
        for (int nt = 0; nt < 8; nt++) {
            sf[nt][0] *= 8.f; sf[nt][1] *= 8.f; sf[nt][2] *= 8.f; sf[nt][3] *= 8.f;
            r0m = fmaxf(r0m, fmaxf(sf[nt][0], sf[nt][1]));
            r1m = fmaxf(r1m, fmaxf(sf[nt][2], sf[nt][3]));
        }
        r0m = fmaxf(r0m, __shfl_xor_sync(0xffffffffu, r0m, 1));
        r0m = fmaxf(r0m, __shfl_xor_sync(0xffffffffu, r0m, 2));
        r1m = fmaxf(r1m, __shfl_xor_sync(0xffffffffu, r1m, 1));
        r1m = fmaxf(r1m, __shfl_xor_sync(0xffffffffu, r1m, 2));

        float mn0 = fmaxf(m0, r0m), mn1 = fmaxf(m1, r1m);
        float cr0 = __expf(m0 - mn0), cr1 = __expf(m1 - mn1);
        float s0 = 0.f, s1 = 0.f;
#pragma unroll
        for (int nt = 0; nt < 8; nt++) {
            sf[nt][0] = __expf(sf[nt][0] - mn0);
            sf[nt][1] = __expf(sf[nt][1] - mn0);
            sf[nt][2] = __expf(sf[nt][2] - mn1);
            sf[nt][3] = __expf(sf[nt][3] - mn1);
            s0 += sf[nt][0] + sf[nt][1];
            s1 += sf[nt][2] + sf[nt][3];
        }
        s0 += __shfl_xor_sync(0xffffffffu, s0, 1);
        s0 += __shfl_xor_sync(0xffffffffu, s0, 2);
        s1 += __shfl_xor_sync(0xffffffffu, s1, 1);
        s1 += __shfl_xor_sync(0xffffffffu, s1, 2);
        l0 = l0 * cr0 + s0;  m0 = mn0;
        l1 = l1 * cr1 + s1;  m1 = mn1;
#pragma unroll
        for (int dt = 0; dt < 8; dt++) {
            of[dt][0] *= cr0; of[dt][1] *= cr0;
            of[dt][2] *= cr1; of[dt][3] *= cr1;
        }

        // ---- stage P hi/lo (per-warp-private rows) ----
#pragma unroll
        for (int nt = 0; nt < 8; nt++) {
            int jc = nt * 8 + 2 * t;
            uint32_t hh, ll;
            tf32_split(sf[nt][0], hh, ll);
            Ph[(wr + g) * 68 + jc] = hh;      Pl[(wr + g) * 68 + jc] = ll;
            tf32_split(sf[nt][1], hh, ll);
            Ph[(wr + g) * 68 + jc + 1] = hh;  Pl[(wr + g) * 68 + jc + 1] = ll;
            tf32_split(sf[nt][2], hh, ll);
            Ph[(wr + 8 + g) * 68 + jc] = hh;      Pl[(wr + 8 + g) * 68 + jc] = ll;
            tf32_split(sf[nt][3], hh, ll);
            Ph[(wr + 8 + g) * 68 + jc + 1] = hh;  Pl[(wr + 8 + g) * 68 + jc + 1] = ll;
        }
        __syncwarp();

        // ---- O += P V (3xTF32) ----
#pragma unroll
        for (int ks = 0; ks < 8; ks++) {
            int kb = ks * 8;
            int i0 = (wr + g) * 68 + kb + t;
            int i1 = (wr + 8 + g) * 68 + kb + t;
            uint32_t ah[4] = { Ph[i0], Ph[i1], Ph[i0 + 4], Ph[i1 + 4] };
            uint32_t al[4] = { Pl[i0], Pl[i1], Pl[i0 + 4], Pl[i1 + 4] };
#pragma unroll
            for (int nt = 0; nt < 8; nt++) {
                int j0i = (kb + t) * 68 + nt * 8 + g;
                int j1i = (kb + t + 4) * 68 + nt * 8 + g;
                uint32_t bh[2] = { Vh[j0i], Vh[j1i] };
                uint32_t bl[2] = { Vl[j0i], Vl[j1i] };
                mma3(of[nt], ah, al, bh, bl);
            }
        }

        CP_WAIT1();           // raw stage for tile it+1 complete
        __syncthreads();      // all warps done with hi/lo + see new raw stage
    }

    float inv0 = 1.f / l0, inv1 = 1.f / l1;
    int row0 = b * 2048 + q0 + wr + g;
#pragma unroll
    for (int nt = 0; nt < 8; nt++) {
        int col = h * 64 + nt * 8 + 2 * t;
        *reinterpret_cast<float2*>(O + (size_t)row0 * 1024 + col) =
            make_float2(of[nt][0] * inv0, of[nt][1] * inv0);
        *reinterpret_cast<float2*>(O + (size_t)(row0 + 8) * 1024 + col) =
            make_float2(of[nt][2] * inv1, of[nt][3] * inv1);
    }
}

// ---------------------------------------------------------------------------
extern "C" void kernel_launch(void* const* d_in, const int* in_sizes, int n_in,
                              void* d_out, int out_size) {
    const float* x     = (const float*)d_in[0];   // [2,2048,1024]
    const float* w_q   = (const float*)d_in[1];   // [1024,1024]
    const float* w_vk  = (const float*)d_in[2];   // [1024,2048]
    const float* w_out = (const float*)d_in[3];   // [1024,1024]
    float* out = (float*)d_out;                   // [2,2048,1024]

    float *q, *kv, *ao;
    cudaGetSymbolAddress((void**)&q,  g_q);
    cudaGetSymbolAddress((void**)&kv, g_kv);
    cudaGetSymbolAddress((void**)&ao, g_ao);

    cudaFuncSetAttribute(gemm_3xtf32_kernel,
                         cudaFuncAttributeMaxDynamicSharedMemorySize, GEMM_SMEM);
    cudaFuncSetAttribute(flash_3xtf32_kernel,
                         cudaFuncAttributeMaxDynamicSharedMemorySize, FLASH_SMEM);

    gemm_3xtf32_kernel<<<dim3(8, 32), 256, GEMM_SMEM>>>(x, w_q, q, 4096, 1024, 1024);
    gemm_3xtf32_kernel<<<dim3(16, 32), 256, GEMM_SMEM>>>(x, w_vk, kv, 4096, 2048, 1024);
    flash_3xtf32_kernel<<<dim3(16, 16, 2), 256, FLASH_SMEM>>>(q, kv, ao);
    gemm_3xtf32_kernel<<<dim3(8, 32), 256, GEMM_SMEM>>>(ao, w_out, out, 4096, 1024, 1024);
}

// round 9
// speedup vs baseline: 1.4792x; 1.4792x over previous
#include <cuda_runtime.h>
#include <cuda_fp16.h>
#include <cuda_bf16.h>
#include <cstdint>

// Scratch (static device memory — no cudaMalloc anywhere)
__device__ float g_q [4096u * 1024u];   // Q  = x @ w_q       [4096,1024]
__device__ float g_kv[4096u * 2048u];   // KV = x @ w_vk      [4096,2048]
__device__ float g_ao[4096u * 1024u];   // attention output   [4096,1024]

// ---------------------------------------------------------------------------
// helpers
// ---------------------------------------------------------------------------
__device__ __forceinline__ uint32_t f2tf32(float f) {
    uint32_t u;
    asm("cvt.rna.tf32.f32 %0, %1;" : "=r"(u) : "f"(f));
    return u;
}
__device__ __forceinline__ void tf32_split(float x, uint32_t& hi, uint32_t& lo) {
    hi = f2tf32(x);
    lo = f2tf32(x - __uint_as_float(hi));
}
// fp16 Markidis split of two consecutive-k elements into packed half2 hi/lo.
// lo half of the b32 = first element (lower k), hi half = second (higher k).
__device__ __forceinline__ void f16_split2(float x0, float x1, uint32_t& hi, uint32_t& lo) {
    __half2 h = __floats2half2_rn(x0, x1);
    __half2 l = __floats2half2_rn(x0 - __low2float(h), x1 - __high2float(h));
    hi = *reinterpret_cast<uint32_t*>(&h);
    lo = *reinterpret_cast<uint32_t*>(&l);
}

// tf32 m16n8k8 (validated): A a0=(g,t) a1=(g+8,t) a2=(g,t+4) a3=(g+8,t+4);
// B b0=(t,g) b1=(t+4,g); C c0=(g,2t) c1=(g,2t+1) c2=(g+8,2t) c3=(g+8,2t+1)
__device__ __forceinline__ void mma_tf32(float c[4], const uint32_t a[4], const uint32_t b[2]) {
    asm volatile(
        "mma.sync.aligned.m16n8k8.row.col.f32.tf32.tf32.f32 "
        "{%0,%1,%2,%3}, {%4,%5,%6,%7}, {%8,%9}, {%0,%1,%2,%3};\n"
        : "+f"(c[0]), "+f"(c[1]), "+f"(c[2]), "+f"(c[3])
        : "r"(a[0]), "r"(a[1]), "r"(a[2]), "r"(a[3]), "r"(b[0]), "r"(b[1]));
}
__device__ __forceinline__ void mma3_tf32(float c[4], const uint32_t ah[4], const uint32_t al[4],
                                          const uint32_t bh[2], const uint32_t bl[2]) {
    mma_tf32(c, ah, bl);
    mma_tf32(c, al, bh);
    mma_tf32(c, ah, bh);
}

// fp16 m16n8k16: A (16x16 row-major) a0=(g, 2t|2t+1) a1=(g+8, 2t|2t+1)
//   a2=(g, 2t+8|2t+9) a3=(g+8, 2t+8|2t+9)   [each b32 = 2 halves, k-ascending]
// B (16x8, k-major pairs) b0=(2t|2t+1, g) b1=(2t+8|2t+9, g)
// C same as tf32 k8.
__device__ __forceinline__ void mma_f16(float c[4], const uint32_t a[4], const uint32_t b[2]) {
    asm volatile(
        "mma.sync.aligned.m16n8k16.row.col.f32.f16.f16.f32 "
        "{%0,%1,%2,%3}, {%4,%5,%6,%7}, {%8,%9}, {%0,%1,%2,%3};\n"
        : "+f"(c[0]), "+f"(c[1]), "+f"(c[2]), "+f"(c[3])
        : "r"(a[0]), "r"(a[1]), "r"(a[2]), "r"(a[3]), "r"(b[0]), "r"(b[1]));
}
__device__ __forceinline__ void mma3_f16(float c[4], const uint32_t ah[4], const uint32_t al[4],
                                         const uint32_t bh[2], const uint32_t bl[2]) {
    mma_f16(c, ah, bl);
    mma_f16(c, al, bh);
    mma_f16(c, ah, bh);
}

// ---------------------------------------------------------------------------
// split-fp16 GEMM: C[M,N] = A[M,K] @ B[K,N], row-major fp32 in/out.
// Block 128x128, BK=32 (2 k16-steps), 256 threads = 8 warps (2m x 4n),
// warp tile 64x32. Split at store; half2 packed along k.
//   Ah2/Al2: [128 m][20]   (16 k-pairs + pad4)  -> a-frag banks 20g+t, all 32
//   Bh2/Bl2: [16 kp][136]  (128 n + pad8)       -> b-frag banks 8t+g, all 32
// ---------------------------------------------------------------------------
__global__ void __launch_bounds__(256, 2)
gemm_f16x2_kernel(const float* __restrict__ A, const float* __restrict__ B,
                  float* __restrict__ C, int M, int N, int K) {
    __shared__ uint32_t Ah2[128 * 20];
    __shared__ uint32_t Al2[128 * 20];
    __shared__ uint32_t Bh2[16 * 136];
    __shared__ uint32_t Bl2[16 * 136];

    const int tid  = threadIdx.x;
    const int lane = tid & 31;
    const int warp = tid >> 5;
    const int g = lane >> 2;
    const int t = lane & 3;
    const int wm = warp >> 2;
    const int wn = warp & 3;
    const int bm = blockIdx.y * 128;
    const int bn = blockIdx.x * 128;

    const int ar = tid >> 3;          // 0..31 (A row, step 32)
    const int ac = (tid & 7) << 2;    // 0..28 (A k offset)
    const int kp = tid >> 4;          // 0..15 (B k-pair)
    const int n0 = (tid & 15) << 3;   // 0..120 (B n offset)

    float acc[4][4][4];
#pragma unroll
    for (int i = 0; i < 4; i++)
#pragma unroll
        for (int j = 0; j < 4; j++)
#pragma unroll
            for (int v = 0; v < 4; v++) acc[i][j][v] = 0.f;

    for (int k0 = 0; k0 < K; k0 += 32) {
        // ---- stage A (split at store, pack k-pairs) ----
#pragma unroll
        for (int p = 0; p < 4; p++) {
            int r = ar + p * 32;
            float4 v = *reinterpret_cast<const float4*>(A + (size_t)(bm + r) * K + k0 + ac);
            uint32_t h0, l0, h1, l1;
            f16_split2(v.x, v.y, h0, l0);
            f16_split2(v.z, v.w, h1, l1);
            *reinterpret_cast<uint2*>(&Ah2[r * 20 + (ac >> 1)]) = make_uint2(h0, h1);
            *reinterpret_cast<uint2*>(&Al2[r * 20 + (ac >> 1)]) = make_uint2(l0, l1);
        }
        // ---- stage B (pack across k rows 2kp, 2kp+1) ----
        {
            const float* Bp = B + (size_t)(k0 + 2 * kp) * N + bn + n0;
            float4 r0a = *reinterpret_cast<const float4*>(Bp);
            float4 r0b = *reinterpret_cast<const float4*>(Bp + 4);
            float4 r1a = *reinterpret_cast<const float4*>(Bp + N);
            float4 r1b = *reinterpret_cast<const float4*>(Bp + N + 4);
            uint32_t hi[8], lo[8];
            f16_split2(r0a.x, r1a.x, hi[0], lo[0]);
            f16_split2(r0a.y, r1a.y, hi[1], lo[1]);
            f16_split2(r0a.z, r1a.z, hi[2], lo[2]);
            f16_split2(r0a.w, r1a.w, hi[3], lo[3]);
            f16_split2(r0b.x, r1b.x, hi[4], lo[4]);
            f16_split2(r0b.y, r1b.y, hi[5], lo[5]);
            f16_split2(r0b.z, r1b.z, hi[6], lo[6]);
            f16_split2(r0b.w, r1b.w, hi[7], lo[7]);
            *reinterpret_cast<uint4*>(&Bh2[kp * 136 + n0])     = make_uint4(hi[0], hi[1], hi[2], hi[3]);
            *reinterpret_cast<uint4*>(&Bh2[kp * 136 + n0 + 4]) = make_uint4(hi[4], hi[5], hi[6], hi[7]);
            *reinterpret_cast<uint4*>(&Bl2[kp * 136 + n0])     = make_uint4(lo[0], lo[1], lo[2], lo[3]);
            *reinterpret_cast<uint4*>(&Bl2[kp * 136 + n0 + 4]) = make_uint4(lo[4], lo[5], lo[6], lo[7]);
        }
        __syncthreads();

#pragma unroll
        for (int ks = 0; ks < 2; ks++) {
            const int kb2 = ks * 8;   // k-pair base
            uint32_t afh[4][4], afl[4][4], bfh[4][2], bfl[4][2];
#pragma unroll
            for (int mt = 0; mt < 4; mt++) {
                int r0 = wm * 64 + mt * 16;
                int i0 = (r0 + g) * 20 + kb2 + t;
                int i1 = (r0 + 8 + g) * 20 + kb2 + t;
                afh[mt][0] = Ah2[i0];     afl[mt][0] = Al2[i0];
                afh[mt][1] = Ah2[i1];     afl[mt][1] = Al2[i1];
                afh[mt][2] = Ah2[i0 + 4]; afl[mt][2] = Al2[i0 + 4];
                afh[mt][3] = Ah2[i1 + 4]; afl[mt][3] = Al2[i1 + 4];
            }
#pragma unroll
            for (int nt = 0; nt < 4; nt++) {
                int c0 = wn * 32 + nt * 8;
                int i0 = (kb2 + t) * 136 + c0 + g;
                int i1 = (kb2 + t + 4) * 136 + c0 + g;
                bfh[nt][0] = Bh2[i0]; bfl[nt][0] = Bl2[i0];
                bfh[nt][1] = Bh2[i1]; bfl[nt][1] = Bl2[i1];
            }
#pragma unroll
            for (int mt = 0; mt < 4; mt++)
#pragma unroll
                for (int nt = 0; nt < 4; nt++)
                    mma3_f16(acc[mt][nt], afh[mt], afl[mt], bfh[nt], bfl[nt]);
        }
        __syncthreads();
    }

#pragma unroll
    for (int mt = 0; mt < 4; mt++) {
        int row = bm + wm * 64 + mt * 16 + g;
#pragma unroll
        for (int nt = 0; nt < 4; nt++) {
            int col = bn + wn * 32 + nt * 8 + 2 * t;
            *reinterpret_cast<float2*>(C + (size_t)row * N + col) =
                make_float2(acc[mt][nt][0], acc[mt][nt][1]);
            *reinterpret_cast<float2*>(C + (size_t)(row + 8) * N + col) =
                make_float2(acc[mt][nt][2], acc[mt][nt][3]);
        }
    }
}

// ---------------------------------------------------------------------------
// Flash attention: S = QK^T in split-fp16 (m16n8k16), PV in 3xTF32 (m16n8k8).
// Block = 128 threads (4 warps), 64 q-rows; warp owns 16 rows.
// smem (u32): Kh2/Kl2 [64][36] (32 d-pairs+pad), Vh/Vl [64][68],
//             Ph/Pl [64][68] (P tf32; Ph doubles as fp32 Q staging).
// NOTE: reference MULTIPLIES logits by sqrt(64)=8.
// ---------------------------------------------------------------------------
#define KT2 (64 * 36)
#define FT  (64 * 68)
#define FLASH_SMEM ((2 * KT2 + 4 * FT) * 4)   // 88064 bytes

__global__ void __launch_bounds__(128, 2)
flash_f16_kernel(const float* __restrict__ Q, const float* __restrict__ KV,
                 float* __restrict__ O) {
    extern __shared__ uint32_t sm[];
    uint32_t* Kh2 = sm;
    uint32_t* Kl2 = sm + KT2;
    uint32_t* Vh  = sm + 2 * KT2;
    uint32_t* Vl  = Vh + FT;
    uint32_t* Ph  = Vh + 2 * FT;
    uint32_t* Pl  = Vh + 3 * FT;

    const int tid  = threadIdx.x;
    const int lane = tid & 31;
    const int warp = tid >> 5;
    const int g = lane >> 2;
    const int t = lane & 3;
    const int wr = warp * 16;

    const int b  = blockIdx.z;
    const int h  = blockIdx.y;
    const int q0 = blockIdx.x * 64;

    // ---- stage Q tile 64x64 fp32 into Ph, then build fp16 hi/lo A-frags ----
    float* Phf = reinterpret_cast<float*>(Ph);
#pragma unroll
    for (int p = 0; p < 8; p++) {
        int idx = tid + p * 128;
        int r = idx >> 4;
        int c = (idx & 15) << 2;
        *reinterpret_cast<float4*>(Phf + r * 68 + c) =
            *reinterpret_cast<const float4*>(
                Q + (size_t)(b * 2048 + q0 + r) * 1024 + h * 64 + c);
    }
    __syncthreads();

    uint32_t qh[4][4], ql[4][4];
#pragma unroll
    for (int ks = 0; ks < 4; ks++) {
        int cb = ks * 16 + 2 * t;
        const float* r0p = Phf + (wr + g) * 68;
        const float* r1p = Phf + (wr + 8 + g) * 68;
        f16_split2(r0p[cb],     r0p[cb + 1], qh[ks][0], ql[ks][0]);
        f16_split2(r1p[cb],     r1p[cb + 1], qh[ks][1], ql[ks][1]);
        f16_split2(r0p[cb + 8], r0p[cb + 9], qh[ks][2], ql[ks][2]);
        f16_split2(r1p[cb + 8], r1p[cb + 9], qh[ks][3], ql[ks][3]);
    }
    __syncthreads();   // Ph free for P staging

    float of[8][4];
#pragma unroll
    for (int i = 0; i < 8; i++)
#pragma unroll
        for (int v = 0; v < 4; v++) of[i][v] = 0.f;
    float m0 = -1e30f, m1 = -1e30f, l0 = 0.f, l1 = 0.f;

    const float* Kb = KV + (size_t)b * 2048 * 2048 + h * 64;

    for (int j0 = 0; j0 < 2048; j0 += 64) {
        // ---- load K (fp16 split, k-pairs) and V (tf32 split) tiles ----
#pragma unroll
        for (int p = 0; p < 8; p++) {
            int idx = tid + p * 128;
            int r = idx >> 4;
            int c = (idx & 15) << 2;
            const float* kp = Kb + (size_t)(j0 + r) * 2048 + c;
            float4 k4 = *reinterpret_cast<const float4*>(kp);
            uint32_t h0, l0u, h1, l1u;
            f16_split2(k4.x, k4.y, h0, l0u);
            f16_split2(k4.z, k4.w, h1, l1u);
            *reinterpret_cast<uint2*>(&Kh2[r * 36 + (c >> 1)]) = make_uint2(h0, h1);
            *reinterpret_cast<uint2*>(&Kl2[r * 36 + (c >> 1)]) = make_uint2(l0u, l1u);
            float4 v4 = *reinterpret_cast<const float4*>(kp + 1024);
            uint4 hh, ll;
            tf32_split(v4.x, hh.x, ll.x); tf32_split(v4.y, hh.y, ll.y);
            tf32_split(v4.z, hh.z, ll.z); tf32_split(v4.w, hh.w, ll.w);
            *reinterpret_cast<uint4*>(&Vh[r * 68 + c]) = hh;
            *reinterpret_cast<uint4*>(&Vl[r * 68 + c]) = ll;
        }
        __syncthreads();

        // ---- S = Q K^T (split-fp16, 4 k16-steps x 8 j-tiles) ----
        float sf[8][4];
#pragma unroll
        for (int nt = 0; nt < 8; nt++)
#pragma unroll
            for (int v = 0; v < 4; v++) sf[nt][v] = 0.f;
#pragma unroll
        for (int ks = 0; ks < 4; ks++) {
            int kb2 = ks * 8;
#pragma unroll
            for (int nt = 0; nt < 8; nt++) {
                int i0 = (nt * 8 + g) * 36 + kb2 + t;
                uint32_t bh[2] = { Kh2[i0], Kh2[i0 + 4] };
                uint32_t bl[2] = { Kl2[i0], Kl2[i0 + 4] };
                mma3_f16(sf[nt], qh[ks], ql[ks], bh, bl);
            }
        }

        // ---- online softmax (x8 scale; rows g and g+8) ----
        float r0m = -1e30f, r1m = -1e30f;
#pragma unroll
        for (int nt = 0; nt < 8; nt++) {
            sf[nt][0] *= 8.f; sf[nt][1] *= 8.f; sf[nt][2] *= 8.f; sf[nt][3] *= 8.f;
            r0m = fmaxf(r0m, fmaxf(sf[nt][0], sf[nt][1]));
            r1m = fmaxf(r1m, fmaxf(sf[nt][2], sf[nt][3]));
        }
        r0m = fmaxf(r0m, __shfl_xor_sync(0xffffffffu, r0m, 1));
        r0m = fmaxf(r0m, __shfl_xor_sync(0xffffffffu, r0m, 2));
        r1m = fmaxf(r1m, __shfl_xor_sync(0xffffffffu, r1m, 1));
        r1m = fmaxf(r1m, __shfl_xor_sync(0xffffffffu, r1m, 2));

        float mn0 = fmaxf(m0, r0m), mn1 = fmaxf(m1, r1m);
        float cr0 = __expf(m0 - mn0), cr1 = __expf(m1 - mn1);
        float s0 = 0.f, s1 = 0.f;
#pragma unroll
        for (int nt = 0; nt < 8; nt++) {
            sf[nt][0] = __expf(sf[nt][0] - mn0);
            sf[nt][1] = __expf(sf[nt][1] - mn0);
            sf[nt][2] = __expf(sf[nt][2] - mn1);
            sf[nt][3] = __expf(sf[nt][3] - mn1);
            s0 += sf[nt][0] + sf[nt][1];
            s1 += sf[nt][2] + sf[nt][3];
        }
        s0 += __shfl_xor_sync(0xffffffffu, s0, 1);
        s0 += __shfl_xor_sync(0xffffffffu, s0, 2);
        s1 += __shfl_xor_sync(0xffffffffu, s1, 1);
        s1 += __shfl_xor_sync(0xffffffffu, s1, 2);
        l0 = l0 * cr0 + s0;  m0 = mn0;
        l1 = l1 * cr1 + s1;  m1 = mn1;
#pragma unroll
        for (int dt = 0; dt < 8; dt++) {
            of[dt][0] *= cr0; of[dt][1] *= cr0;
            of[dt][2] *= cr1; of[dt][3] *= cr1;
        }

        // ---- stage P hi/lo tf32 (per-warp-private rows) ----
#pragma unroll
        for (int nt = 0; nt < 8; nt++) {
            int jc = nt * 8 + 2 * t;
            uint32_t hh, ll;
            tf32_split(sf[nt][0], hh, ll);
            Ph[(wr + g) * 68 + jc] = hh;      Pl[(wr + g) * 68 + jc] = ll;
            tf32_split(sf[nt][1], hh, ll);
            Ph[(wr + g) * 68 + jc + 1] = hh;  Pl[(wr + g) * 68 + jc + 1] = ll;
            tf32_split(sf[nt][2], hh, ll);
            Ph[(wr + 8 + g) * 68 + jc] = hh;      Pl[(wr + 8 + g) * 68 + jc] = ll;
            tf32_split(sf[nt][3], hh, ll);
            Ph[(wr + 8 + g) * 68 + jc + 1] = hh;  Pl[(wr + 8 + g) * 68 + jc + 1] = ll;
        }
        __syncwarp();

        // ---- O += P V (3xTF32, 8 k8-steps x 8 d-tiles) ----
#pragma unroll
        for (int ks = 0; ks < 8; ks++) {
            int kb = ks * 8;
            int i0 = (wr + g) * 68 + kb + t;
            int i1 = (wr + 8 + g) * 68 + kb + t;
            uint32_t ah[4] = { Ph[i0], Ph[i1], Ph[i0 + 4], Ph[i1 + 4] };
            uint32_t al[4] = { Pl[i0], Pl[i1], Pl[i0 + 4], Pl[i1 + 4] };
#pragma unroll
            for (int nt = 0; nt < 8; nt++) {
                int j0i = (kb + t) * 68 + nt * 8 + g;
                int j1i = (kb + t + 4) * 68 + nt * 8 + g;
                uint32_t bh[2] = { Vh[j0i], Vh[j1i] };
                uint32_t bl[2] = { Vl[j0i], Vl[j1i] };
                mma3_tf32(of[nt], ah, al, bh, bl);
            }
        }
        __syncthreads();   // before K/V overwrite
    }

    float inv0 = 1.f / l0, inv1 = 1.f / l1;
    int row0 = b * 2048 + q0 + wr + g;
#pragma unroll
    for (int nt = 0; nt < 8; nt++) {
        int col = h * 64 + nt * 8 + 2 * t;
        *reinterpret_cast<float2*>(O + (size_t)row0 * 1024 + col) =
            make_float2(of[nt][0] * inv0, of[nt][1] * inv0);
        *reinterpret_cast<float2*>(O + (size_t)(row0 + 8) * 1024 + col) =
            make_float2(of[nt][2] * inv1, of[nt][3] * inv1);
    }
}

// ---------------------------------------------------------------------------
extern "C" void kernel_launch(void* const* d_in, const int* in_sizes, int n_in,
                              void* d_out, int out_size) {
    const float* x     = (const float*)d_in[0];   // [2,2048,1024]
    const float* w_q   = (const float*)d_in[1];   // [1024,1024]
    const float* w_vk  = (const float*)d_in[2];   // [1024,2048]
    const float* w_out = (const float*)d_in[3];   // [1024,1024]
    float* out = (float*)d_out;                   // [2,2048,1024]

    float *q, *kv, *ao;
    cudaGetSymbolAddress((void**)&q,  g_q);
    cudaGetSymbolAddress((void**)&kv, g_kv);
    cudaGetSymbolAddress((void**)&ao, g_ao);

    cudaFuncSetAttribute(flash_f16_kernel,
                         cudaFuncAttributeMaxDynamicSharedMemorySize, FLASH_SMEM);

    gemm_f16x2_kernel<<<dim3(8, 32),  256>>>(x, w_q, q, 4096, 1024, 1024);
    gemm_f16x2_kernel<<<dim3(16, 32), 256>>>(x, w_vk, kv, 4096, 2048, 1024);
    flash_f16_kernel<<<dim3(32, 16, 2), 128, FLASH_SMEM>>>(q, kv, ao);
    gemm_f16x2_kernel<<<dim3(8, 32),  256>>>(ao, w_out, out, 4096, 1024, 1024);
}

// round 11
// speedup vs baseline: 1.9068x; 1.2891x over previous
#include <cuda_runtime.h>
#include <cuda_fp16.h>
#include <cuda_bf16.h>
#include <cstdint>

// Scratch (static device memory — no cudaMalloc anywhere)
__device__ float g_q [4096u * 1024u];   // Q  = x @ w_q       [4096,1024]
__device__ float g_kv[4096u * 2048u];   // KV = x @ w_vk      [4096,2048]
__device__ float g_ao[4096u * 1024u];   // attention output   [4096,1024]

// ---------------------------------------------------------------------------
// helpers
// ---------------------------------------------------------------------------
// fp16 Markidis split of two consecutive-k elements into packed half2 hi/lo.
// low half of the b32 = first element (lower k).
__device__ __forceinline__ void f16_split2(float x0, float x1, uint32_t& hi, uint32_t& lo) {
    __half2 h = __floats2half2_rn(x0, x1);
    __half2 l = __floats2half2_rn(x0 - __low2float(h), x1 - __high2float(h));
    hi = *reinterpret_cast<uint32_t*>(&h);
    lo = *reinterpret_cast<uint32_t*>(&l);
}

// fp16 m16n8k16 (validated): A a0=(g,2t|2t+1) a1=(g+8,..) a2=(g,2t+8|2t+9) a3=(g+8,..)
// B b0=(2t|2t+1, g) b1=(2t+8|2t+9, g); C c0=(g,2t) c1=(g,2t+1) c2=(g+8,2t) c3=(g+8,2t+1)
__device__ __forceinline__ void mma_f16(float c[4], const uint32_t a[4], const uint32_t b[2]) {
    asm volatile(
        "mma.sync.aligned.m16n8k16.row.col.f32.f16.f16.f32 "
        "{%0,%1,%2,%3}, {%4,%5,%6,%7}, {%8,%9}, {%0,%1,%2,%3};\n"
        : "+f"(c[0]), "+f"(c[1]), "+f"(c[2]), "+f"(c[3])
        : "r"(a[0]), "r"(a[1]), "r"(a[2]), "r"(a[3]), "r"(b[0]), "r"(b[1]));
}
__device__ __forceinline__ void mma3_f16(float c[4], const uint32_t ah[4], const uint32_t al[4],
                                         const uint32_t bh[2], const uint32_t bl[2]) {
    mma_f16(c, ah, bl);
    mma_f16(c, al, bh);
    mma_f16(c, ah, bh);
}
__device__ __forceinline__ uint32_t smem_u32(const void* p) {
    return (uint32_t)__cvta_generic_to_shared(p);
}
__device__ __forceinline__ void cp16(uint32_t saddr, const void* gptr) {
    asm volatile("cp.async.cg.shared.global [%0], [%1], 16;\n" :: "r"(saddr), "l"(gptr));
}
#define CP_COMMIT() asm volatile("cp.async.commit_group;\n" ::: "memory")
#define CP_WAIT1()  asm volatile("cp.async.wait_group 1;\n" ::: "memory")

// ---------------------------------------------------------------------------
// split-fp16 GEMM with cp.async double-buffered RAW staging + split-at-store.
// C[M,N]=A[M,K]@B[K,N] row-major fp32. Block 128x128, BK=32, 256 thr (8 warps,
// 2m x 4n), warp tile 64x32.
// smem (units: float/u32):
//   raw stage s: A[128][36] + B[32][132]         (8832 per stage, 2 stages)
//   Ah2/Al2 [128][20] (k-pairs), Bh2/Bl2 [16][136]
// ---------------------------------------------------------------------------
#define GAR (128 * 36)
#define GBR (32 * 132)
#define GRS (GAR + GBR)            // 8832
#define GAH (128 * 20)             // 2560
#define GBH (16 * 136)             // 2176
#define GEMM_SMEM ((2 * GRS + 2 * GAH + 2 * GBH) * 4)   // 108544 bytes

__global__ void __launch_bounds__(256, 2)
gemm_f16x2_kernel(const float* __restrict__ A, const float* __restrict__ B,
                  float* __restrict__ C, int M, int N, int K) {
    extern __shared__ float smf[];
    const uint32_t sbase = smem_u32(smf);
    uint32_t* Ah2 = reinterpret_cast<uint32_t*>(smf + 2 * GRS);
    uint32_t* Al2 = Ah2 + GAH;
    uint32_t* Bh2 = Al2 + GAH;
    uint32_t* Bl2 = Bh2 + GBH;

    const int tid  = threadIdx.x;
    const int lane = tid & 31;
    const int warp = tid >> 5;
    const int g = lane >> 2;
    const int t = lane & 3;
    const int wm = warp >> 2;
    const int wn = warp & 3;
    const int bm = blockIdx.y * 128;
    const int bn = blockIdx.x * 128;

    const int ar = tid >> 3;          // 0..31 (A row, step 32)
    const int ac = (tid & 7) << 2;    // 0..28

    float acc[4][4][4];
#pragma unroll
    for (int i = 0; i < 4; i++)
#pragma unroll
        for (int j = 0; j < 4; j++)
#pragma unroll
            for (int v = 0; v < 4; v++) acc[i][j][v] = 0.f;

    // cp.async one raw k-stage (A 128x32, B 32x128)
    const int brr = tid >> 5;          // 0..7 (B row, step 8)
    const int bcc = lane << 2;         // 0..124
    auto load_stage = [&](int k0, int s) {
        uint32_t abase = sbase + (uint32_t)(s * GRS) * 4u;
        uint32_t bbase = abase + (uint32_t)GAR * 4u;
#pragma unroll
        for (int p = 0; p < 4; p++) {
            int r = ar + p * 32;
            cp16(abase + (uint32_t)(r * 36 + ac) * 4u,
                 A + (size_t)(bm + r) * K + k0 + ac);
        }
#pragma unroll
        for (int p = 0; p < 4; p++) {
            int r = brr + p * 8;
            cp16(bbase + (uint32_t)(r * 132 + bcc) * 4u,
                 B + (size_t)(k0 + r) * N + bn + bcc);
        }
    };

    // split raw stage s -> hi/lo buffers
    auto split_stage = [&](int s) {
        const float* Araw = smf + s * GRS;
        const float* Braw = Araw + GAR;
        // A: 128 rows x 8 c-groups = 1024 tasks
#pragma unroll
        for (int p = 0; p < 4; p++) {
            int idx = tid + p * 256;
            int r  = idx >> 3;
            int cg = (idx & 7) << 2;
            float4 v = *reinterpret_cast<const float4*>(Araw + r * 36 + cg);
            uint32_t h0, l0, h1, l1;
            f16_split2(v.x, v.y, h0, l0);
            f16_split2(v.z, v.w, h1, l1);
            *reinterpret_cast<uint2*>(&Ah2[r * 20 + (cg >> 1)]) = make_uint2(h0, h1);
            *reinterpret_cast<uint2*>(&Al2[r * 20 + (cg >> 1)]) = make_uint2(l0, l1);
        }
        // B: 16 k-pairs x 32 n-groups = 512 tasks
#pragma unroll
        for (int p = 0; p < 2; p++) {
            int idx = tid + p * 256;
            int kp = idx >> 5;
            int ng = (idx & 31) << 2;
            float4 r0 = *reinterpret_cast<const float4*>(Braw + (2 * kp) * 132 + ng);
            float4 r1 = *reinterpret_cast<const float4*>(Braw + (2 * kp + 1) * 132 + ng);
            uint32_t hi[4], lo[4];
            f16_split2(r0.x, r1.x, hi[0], lo[0]);
            f16_split2(r0.y, r1.y, hi[1], lo[1]);
            f16_split2(r0.z, r1.z, hi[2], lo[2]);
            f16_split2(r0.w, r1.w, hi[3], lo[3]);
            *reinterpret_cast<uint4*>(&Bh2[kp * 136 + ng]) = make_uint4(hi[0], hi[1], hi[2], hi[3]);
            *reinterpret_cast<uint4*>(&Bl2[kp * 136 + ng]) = make_uint4(lo[0], lo[1], lo[2], lo[3]);
        }
    };

    const int nk = K / 32;
    load_stage(0, 0);  CP_COMMIT();
    load_stage(32, 1); CP_COMMIT();
    CP_WAIT1();
    __syncthreads();      // raw0 visible
    split_stage(0);
    __syncthreads();      // hi/lo ready

    for (int i = 0; i < nk; i++) {
        // ---- MMA tile i from hi/lo ----
#pragma unroll
        for (int ks = 0; ks < 2; ks++) {
            const int kb2 = ks * 8;
            uint32_t afh[4][4], afl[4][4], bfh[4][2], bfl[4][2];
#pragma unroll
            for (int mt = 0; mt < 4; mt++) {
                int r0 = wm * 64 + mt * 16;
                int i0 = (r0 + g) * 20 + kb2 + t;
                int i1 = (r0 + 8 + g) * 20 + kb2 + t;
                afh[mt][0] = Ah2[i0];     afl[mt][0] = Al2[i0];
                afh[mt][1] = Ah2[i1];     afl[mt][1] = Al2[i1];
                afh[mt][2] = Ah2[i0 + 4]; afl[mt][2] = Al2[i0 + 4];
                afh[mt][3] = Ah2[i1 + 4]; afl[mt][3] = Al2[i1 + 4];
            }
#pragma unroll
            for (int nt = 0; nt < 4; nt++) {
                int c0 = wn * 32 + nt * 8;
                int i0 = (kb2 + t) * 136 + c0 + g;
                int i1 = (kb2 + t + 4) * 136 + c0 + g;
                bfh[nt][0] = Bh2[i0]; bfl[nt][0] = Bl2[i0];
                bfh[nt][1] = Bh2[i1]; bfl[nt][1] = Bl2[i1];
            }
#pragma unroll
            for (int mt = 0; mt < 4; mt++)
#pragma unroll
                for (int nt = 0; nt < 4; nt++)
                    mma3_f16(acc[mt][nt], afh[mt], afl[mt], bfh[nt], bfl[nt]);
        }
        __syncthreads();                        // hi/lo consumed
        if (i + 2 < nk) load_stage((i + 2) * 32, i & 1);   // reuse slot of raw(i)
        CP_COMMIT();
        CP_WAIT1();                             // raw(i+1) arrived
        __syncthreads();                        // raw(i+1) visible
        if (i + 1 < nk) split_stage((i + 1) & 1);
        __syncthreads();                        // hi/lo ready for i+1
    }

#pragma unroll
    for (int mt = 0; mt < 4; mt++) {
        int row = bm + wm * 64 + mt * 16 + g;
#pragma unroll
        for (int nt = 0; nt < 4; nt++) {
            int col = bn + wn * 32 + nt * 8 + 2 * t;
            *reinterpret_cast<float2*>(C + (size_t)row * N + col) =
                make_float2(acc[mt][nt][0], acc[mt][nt][1]);
            *reinterpret_cast<float2*>(C + (size_t)(row + 8) * N + col) =
                make_float2(acc[mt][nt][2], acc[mt][nt][3]);
        }
    }
}

// ---------------------------------------------------------------------------
// Flash attention, all-fp16-split MMA. Block = 128 threads (4 warps), 64 q-rows.
// S = QK^T: pairs along d;  PV: pairs along j (P packed at store, V pair-packed
// across rows at staging).
// smem (u32): Kh2/Kl2 [64][36], Vh2/Vl2 [32 jp][72], Ph2/Pl2 [64][36]
//   (Ph2+Pl2 region doubles as fp32 Q staging, 64x68 floats <= 4608)
// NOTE: reference MULTIPLIES logits by sqrt(64)=8.
// ---------------------------------------------------------------------------
#define KT2 (64 * 36)
#define VT2 (32 * 72)
#define PT2 (64 * 36)
#define FLASH_SMEM ((2 * KT2 + 2 * VT2 + 2 * PT2) * 4)   // 55296 bytes

__global__ void __launch_bounds__(128, 3)
flash_f16_kernel(const float* __restrict__ Q, const float* __restrict__ KV,
                 float* __restrict__ O) {
    extern __shared__ uint32_t sm[];
    uint32_t* Kh2 = sm;
    uint32_t* Kl2 = sm + KT2;
    uint32_t* Vh2 = sm + 2 * KT2;
    uint32_t* Vl2 = Vh2 + VT2;
    uint32_t* Ph2 = Vh2 + 2 * VT2;
    uint32_t* Pl2 = Ph2 + PT2;

    const int tid  = threadIdx.x;
    const int lane = tid & 31;
    const int warp = tid >> 5;
    const int g = lane >> 2;
    const int t = lane & 3;
    const int wr = warp * 16;

    const int b  = blockIdx.z;
    const int h  = blockIdx.y;
    const int q0 = blockIdx.x * 64;

    // ---- stage Q tile 64x64 fp32 into P region, build fp16 hi/lo A-frags ----
    float* Phf = reinterpret_cast<float*>(Ph2);
#pragma unroll
    for (int p = 0; p < 8; p++) {
        int idx = tid + p * 128;
        int r = idx >> 4;
        int c = (idx & 15) << 2;
        *reinterpret_cast<float4*>(Phf + r * 68 + c) =
            *reinterpret_cast<const float4*>(
                Q + (size_t)(b * 2048 + q0 + r) * 1024 + h * 64 + c);
    }
    __syncthreads();

    uint32_t qh[4][4], ql[4][4];
#pragma unroll
    for (int ks = 0; ks < 4; ks++) {
        int cb = ks * 16 + 2 * t;
        const float* r0p = Phf + (wr + g) * 68;
        const float* r1p = Phf + (wr + 8 + g) * 68;
        f16_split2(r0p[cb],     r0p[cb + 1], qh[ks][0], ql[ks][0]);
        f16_split2(r1p[cb],     r1p[cb + 1], qh[ks][1], ql[ks][1]);
        f16_split2(r0p[cb + 8], r0p[cb + 9], qh[ks][2], ql[ks][2]);
        f16_split2(r1p[cb + 8], r1p[cb + 9], qh[ks][3], ql[ks][3]);
    }
    __syncthreads();   // P region free

    float of[8][4];
#pragma unroll
    for (int i = 0; i < 8; i++)
#pragma unroll
        for (int v = 0; v < 4; v++) of[i][v] = 0.f;
    float m0 = -1e30f, m1 = -1e30f, l0 = 0.f, l1 = 0.f;

    const float* Kb = KV + (size_t)b * 2048 * 2048 + h * 64;

    for (int j0 = 0; j0 < 2048; j0 += 64) {
        // ---- K tile: fp16 split, pairs along d ----
#pragma unroll
        for (int p = 0; p < 8; p++) {
            int idx = tid + p * 128;
            int r = idx >> 4;
            int c = (idx & 15) << 2;
            float4 k4 = *reinterpret_cast<const float4*>(Kb + (size_t)(j0 + r) * 2048 + c);
            uint32_t h0, l0u, h1, l1u;
            f16_split2(k4.x, k4.y, h0, l0u);
            f16_split2(k4.z, k4.w, h1, l1u);
            *reinterpret_cast<uint2*>(&Kh2[r * 36 + (c >> 1)]) = make_uint2(h0, h1);
            *reinterpret_cast<uint2*>(&Kl2[r * 36 + (c >> 1)]) = make_uint2(l0u, l1u);
        }
        // ---- V tile: fp16 split, pairs ACROSS j rows: Vh2[jp][d] ----
#pragma unroll
        for (int p = 0; p < 4; p++) {
            int idx = tid + p * 128;
            int jp = idx >> 4;               // 0..31
            int c  = (idx & 15) << 2;        // 0..60
            const float* vp = Kb + (size_t)(j0 + 2 * jp) * 2048 + 1024 + c;
            float4 v0 = *reinterpret_cast<const float4*>(vp);
            float4 v1 = *reinterpret_cast<const float4*>(vp + 2048);
            uint32_t hi[4], lo[4];
            f16_split2(v0.x, v1.x, hi[0], lo[0]);
            f16_split2(v0.y, v1.y, hi[1], lo[1]);
            f16_split2(v0.z, v1.z, hi[2], lo[2]);
            f16_split2(v0.w, v1.w, hi[3], lo[3]);
            *reinterpret_cast<uint4*>(&Vh2[jp * 72 + c]) = make_uint4(hi[0], hi[1], hi[2], hi[3]);
            *reinterpret_cast<uint4*>(&Vl2[jp * 72 + c]) = make_uint4(lo[0], lo[1], lo[2], lo[3]);
        }
        __syncthreads();

        // ---- S = Q K^T (split-fp16, 4 k16-steps x 8 j-tiles) ----
        float sf[8][4];
#pragma unroll
        for (int nt = 0; nt < 8; nt++)
#pragma unroll
            for (int v = 0; v < 4; v++) sf[nt][v] = 0.f;
#pragma unroll
        for (int ks = 0; ks < 4; ks++) {
            int kb2 = ks * 8;
#pragma unroll
            for (int nt = 0; nt < 8; nt++) {
                int i0 = (nt * 8 + g) * 36 + kb2 + t;
                uint32_t bh[2] = { Kh2[i0], Kh2[i0 + 4] };
                uint32_t bl[2] = { Kl2[i0], Kl2[i0 + 4] };
                mma3_f16(sf[nt], qh[ks], ql[ks], bh, bl);
            }
        }

        // ---- online softmax (x8 scale; rows g and g+8) ----
        float r0m = -1e30f, r1m = -1e30f;
#pragma unroll
        for (int nt = 0; nt < 8; nt++) {
            sf[nt][0] *= 8.f; sf[nt][1] *= 8.f; sf[nt][2] *= 8.f; sf[nt][3] *= 8.f;
            r0m = fmaxf(r0m, fmaxf(sf[nt][0], sf[nt][1]));
            r1m = fmaxf(r1m, fmaxf(sf[nt][2], sf[nt][3]));
        }
        r0m = fmaxf(r0m, __shfl_xor_sync(0xffffffffu, r0m, 1));
        r0m = fmaxf(r0m, __shfl_xor_sync(0xffffffffu, r0m, 2));
        r1m = fmaxf(r1m, __shfl_xor_sync(0xffffffffu, r1m, 1));
        r1m = fmaxf(r1m, __shfl_xor_sync(0xffffffffu, r1m, 2));

        float mn0 = fmaxf(m0, r0m), mn1 = fmaxf(m1, r1m);
        float cr0 = __expf(m0 - mn0), cr1 = __expf(m1 - mn1);
        float s0 = 0.f, s1 = 0.f;
#pragma unroll
        for (int nt = 0; nt < 8; nt++) {
            sf[nt][0] = __expf(sf[nt][0] - mn0);
            sf[nt][1] = __expf(sf[nt][1] - mn0);
            sf[nt][2] = __expf(sf[nt][2] - mn1);
            sf[nt][3] = __expf(sf[nt][3] - mn1);
            s0 += sf[nt][0] + sf[nt][1];
            s1 += sf[nt][2] + sf[nt][3];
        }
        s0 += __shfl_xor_sync(0xffffffffu, s0, 1);
        s0 += __shfl_xor_sync(0xffffffffu, s0, 2);
        s1 += __shfl_xor_sync(0xffffffffu, s1, 1);
        s1 += __shfl_xor_sync(0xffffffffu, s1, 2);
        l0 = l0 * cr0 + s0;  m0 = mn0;
        l1 = l1 * cr1 + s1;  m1 = mn1;
#pragma unroll
        for (int dt = 0; dt < 8; dt++) {
            of[dt][0] *= cr0; of[dt][1] *= cr0;
            of[dt][2] *= cr1; of[dt][3] *= cr1;
        }

        // ---- stage P fp16 hi/lo, packed along j (pair idx nt*4+t) ----
#pragma unroll
        for (int nt = 0; nt < 8; nt++) {
            uint32_t hh, ll;
            f16_split2(sf[nt][0], sf[nt][1], hh, ll);
            Ph2[(wr + g) * 36 + nt * 4 + t] = hh;
            Pl2[(wr + g) * 36 + nt * 4 + t] = ll;
            f16_split2(sf[nt][2], sf[nt][3], hh, ll);
            Ph2[(wr + 8 + g) * 36 + nt * 4 + t] = hh;
            Pl2[(wr + 8 + g) * 36 + nt * 4 + t] = ll;
        }
        __syncwarp();

        // ---- O += P V (split-fp16, 4 k16-steps over j x 8 d-tiles) ----
#pragma unroll
        for (int ks = 0; ks < 4; ks++) {
            int kb2 = ks * 8;
            int i0 = (wr + g) * 36 + kb2 + t;
            int i1 = (wr + 8 + g) * 36 + kb2 + t;
            uint32_t ah[4] = { Ph2[i0], Ph2[i1], Ph2[i0 + 4], Ph2[i1 + 4] };
            uint32_t al[4] = { Pl2[i0], Pl2[i1], Pl2[i0 + 4], Pl2[i1 + 4] };
#pragma unroll
            for (int nt = 0; nt < 8; nt++) {
                int j0i = (kb2 + t) * 72 + nt * 8 + g;
                int j1i = (kb2 + t + 4) * 72 + nt * 8 + g;
                uint32_t bh[2] = { Vh2[j0i], Vh2[j1i] };
                uint32_t bl[2] = { Vl2[j0i], Vl2[j1i] };
                mma3_f16(of[nt], ah, al, bh, bl);
            }
        }
        __syncthreads();   // before K/V/P overwrite
    }

    float inv0 = 1.f / l0, inv1 = 1.f / l1;
    int row0 = b * 2048 + q0 + wr + g;
#pragma unroll
    for (int nt = 0; nt < 8; nt++) {
        int col = h * 64 + nt * 8 + 2 * t;
        *reinterpret_cast<float2*>(O + (size_t)row0 * 1024 + col) =
            make_float2(of[nt][0] * inv0, of[nt][1] * inv0);
        *reinterpret_cast<float2*>(O + (size_t)(row0 + 8) * 1024 + col) =
            make_float2(of[nt][2] * inv1, of[nt][3] * inv1);
    }
}

// ---------------------------------------------------------------------------
extern "C" void kernel_launch(void* const* d_in, const int* in_sizes, int n_in,
                              void* d_out, int out_size) {
    const float* x     = (const float*)d_in[0];   // [2,2048,1024]
    const float* w_q   = (const float*)d_in[1];   // [1024,1024]
    const float* w_vk  = (const float*)d_in[2];   // [1024,2048]
    const float* w_out = (const float*)d_in[3];   // [1024,1024]
    float* out = (float*)d_out;                   // [2,2048,1024]

    float *q, *kv, *ao;
    cudaGetSymbolAddress((void**)&q,  g_q);
    cudaGetSymbolAddress((void**)&kv, g_kv);
    cudaGetSymbolAddress((void**)&ao, g_ao);

    cudaFuncSetAttribute(gemm_f16x2_kernel,
                         cudaFuncAttributeMaxDynamicSharedMemorySize, GEMM_SMEM);
    cudaFuncSetAttribute(flash_f16_kernel,
                         cudaFuncAttributeMaxDynamicSharedMemorySize, FLASH_SMEM);

    gemm_f16x2_kernel<<<dim3(8, 32),  256, GEMM_SMEM>>>(x, w_q, q, 4096, 1024, 1024);
    gemm_f16x2_kernel<<<dim3(16, 32), 256, GEMM_SMEM>>>(x, w_vk, kv, 4096, 2048, 1024);
    flash_f16_kernel<<<dim3(32, 16, 2), 128, FLASH_SMEM>>>(q, kv, ao);
    gemm_f16x2_kernel<<<dim3(8, 32),  256, GEMM_SMEM>>>(ao, w_out, out, 4096, 1024, 1024);
}

// round 13
// speedup vs baseline: 1.9899x; 1.0436x over previous
#include <cuda_runtime.h>
#include <cuda_fp16.h>
#include <cstdint>

// ---------------------------------------------------------------------------
// Split-fp16 global tensors (static device memory — no cudaMalloc anywhere)
// ---------------------------------------------------------------------------
__device__ __half g_xh [4096u * 1024u];
__device__ __half g_xl [4096u * 1024u];
__device__ uint32_t g_wq_h [512u * 1024u];   // pre-paired across k: u32 = {w[2k],w[2k+1]}
__device__ uint32_t g_wq_l [512u * 1024u];
__device__ uint32_t g_wvk_h[512u * 2048u];
__device__ uint32_t g_wvk_l[512u * 2048u];
__device__ uint32_t g_wo_h [512u * 1024u];
__device__ uint32_t g_wo_l [512u * 1024u];
__device__ __half g_qh [4096u * 1024u];
__device__ __half g_ql [4096u * 1024u];
__device__ __half g_kvh[4096u * 2048u];
__device__ __half g_kvl[4096u * 2048u];
__device__ __half g_aoh[4096u * 1024u];
__device__ __half g_aol[4096u * 1024u];

// ---------------------------------------------------------------------------
// helpers
// ---------------------------------------------------------------------------
// Markidis split of (x0,x1) into packed half2 hi/lo; x0 in LOW half.
__device__ __forceinline__ void f16_split2(float x0, float x1, uint32_t& hi, uint32_t& lo) {
    __half2 h = __floats2half2_rn(x0, x1);
    __half2 l = __floats2half2_rn(x0 - __low2float(h), x1 - __high2float(h));
    hi = *reinterpret_cast<uint32_t*>(&h);
    lo = *reinterpret_cast<uint32_t*>(&l);
}
// fp16 m16n8k16 (validated): A a0=(g,2t|2t+1) a1=(g+8,..) a2=(g,2t+8|2t+9) a3=(g+8,..)
// B b0=(2t|2t+1, g) b1=(2t+8|2t+9, g); C c0=(g,2t) c1=(g,2t+1) c2=(g+8,2t) c3=(g+8,2t+1)
__device__ __forceinline__ void mma_f16(float c[4], const uint32_t a[4], const uint32_t b[2]) {
    asm volatile(
        "mma.sync.aligned.m16n8k16.row.col.f32.f16.f16.f32 "
        "{%0,%1,%2,%3}, {%4,%5,%6,%7}, {%8,%9}, {%0,%1,%2,%3};\n"
        : "+f"(c[0]), "+f"(c[1]), "+f"(c[2]), "+f"(c[3])
        : "r"(a[0]), "r"(a[1]), "r"(a[2]), "r"(a[3]), "r"(b[0]), "r"(b[1]));
}
__device__ __forceinline__ void mma3_f16(float c[4], const uint32_t ah[4], const uint32_t al[4],
                                         const uint32_t bh[2], const uint32_t bl[2]) {
    mma_f16(c, ah, bl);
    mma_f16(c, al, bh);
    mma_f16(c, ah, bh);
}
__device__ __forceinline__ uint32_t smem_u32(const void* p) {
    return (uint32_t)__cvta_generic_to_shared(p);
}
__device__ __forceinline__ void cp16(uint32_t saddr, const void* gptr) {
    asm volatile("cp.async.cg.shared.global [%0], [%1], 16;\n" :: "r"(saddr), "l"(gptr));
}
#define CP_COMMIT() asm volatile("cp.async.commit_group;\n" ::: "memory")
#define CP_WAIT0()  asm volatile("cp.async.wait_group 0;\n" ::: "memory")

// ---------------------------------------------------------------------------
// presplit kernels (run once; pure bandwidth)
// ---------------------------------------------------------------------------
__global__ void presplit_plain(const float* __restrict__ x, __half* __restrict__ xh,
                               __half* __restrict__ xl, int n) {
    int i = (blockIdx.x * blockDim.x + threadIdx.x) * 4;
    if (i >= n) return;
    float4 v = *reinterpret_cast<const float4*>(x + i);
    uint32_t h0, l0, h1, l1;
    f16_split2(v.x, v.y, h0, l0);
    f16_split2(v.z, v.w, h1, l1);
    *reinterpret_cast<uint2*>(xh + i) = make_uint2(h0, h1);
    *reinterpret_cast<uint2*>(xl + i) = make_uint2(l0, l1);
}

// w [K][N] f32 -> u32 [K/2][N] pairs across k (low half = lower k)
__global__ void presplit_wpair(const float* __restrict__ w, uint32_t* __restrict__ wh,
                               uint32_t* __restrict__ wl, int K, int N) {
    int idx = blockIdx.x * blockDim.x + threadIdx.x;   // over (K/2)*(N/4)
    int kp = idx / (N >> 2);
    int n4 = (idx % (N >> 2)) * 4;
    if (kp >= (K >> 1)) return;
    const float* r0 = w + (size_t)(2 * kp) * N + n4;
    float4 a = *reinterpret_cast<const float4*>(r0);
    float4 b = *reinterpret_cast<const float4*>(r0 + N);
    uint32_t h[4], l[4];
    f16_split2(a.x, b.x, h[0], l[0]);
    f16_split2(a.y, b.y, h[1], l[1]);
    f16_split2(a.z, b.z, h[2], l[2]);
    f16_split2(a.w, b.w, h[3], l[3]);
    *reinterpret_cast<uint4*>(wh + (size_t)kp * N + n4) = make_uint4(h[0], h[1], h[2], h[3]);
    *reinterpret_cast<uint4*>(wl + (size_t)kp * N + n4) = make_uint4(l[0], l[1], l[2], l[3]);
}

// ---------------------------------------------------------------------------
// split-fp16 GEMM, pre-split inputs, no in-loop conversion.
// C[M,N] = A[M,K] @ B[K,N]. A: row-major half hi/lo. B: pre-paired u32 [K/2][N].
// Block 128x128, BK=32, 256 thr (8 warps 2m x 4n), warp tile 64x32.
// mode 0: C fp32;  mode 1: C split-fp16 (Ch/Cl).
// smem: Ah2/Al2 [128][20] u32 (k-pairs + pad), Bh2/Bl2 [16][136] u32. 37.9KB.
// ---------------------------------------------------------------------------
#define GAH (128 * 20)
#define GBH (16 * 136)

__global__ void __launch_bounds__(256, 2)
gemm_f16p_kernel(const __half* __restrict__ Ah_g, const __half* __restrict__ Al_g,
                 const uint32_t* __restrict__ Bh_g, const uint32_t* __restrict__ Bl_g,
                 float* __restrict__ Cf, __half* __restrict__ Ch, __half* __restrict__ Cl,
                 int M, int N, int K, int mode) {
    __shared__ uint32_t Ah2[GAH], Al2[GAH], Bh2[GBH], Bl2[GBH];
    const uint32_t ah_s = smem_u32(Ah2);
    const uint32_t al_s = smem_u32(Al2);
    const uint32_t bh_s = smem_u32(Bh2);
    const uint32_t bl_s = smem_u32(Bl2);

    const int tid  = threadIdx.x;
    const int lane = tid & 31;
    const int warp = tid >> 5;
    const int g = lane >> 2;
    const int t = lane & 3;
    const int wm = warp >> 2;
    const int wn = warp & 3;
    const int bm = blockIdx.y * 128;
    const int bn = blockIdx.x * 128;

    float acc[4][4][4];
#pragma unroll
    for (int i = 0; i < 4; i++)
#pragma unroll
        for (int j = 0; j < 4; j++)
#pragma unroll
            for (int v = 0; v < 4; v++) acc[i][j][v] = 0.f;

    for (int k0 = 0; k0 < K; k0 += 32) {
        // ---- issue cp.async staging (fp16, no conversion) ----
#pragma unroll
        for (int p = 0; p < 2; p++) {
            int idx = tid + p * 256;           // 512 chunks per A buffer
            int r  = idx >> 2;
            int cu = (idx & 3) << 2;           // u32 offset in row (0,4,8,12)
            cp16(ah_s + (uint32_t)(r * 20 + cu) * 4u,
                 Ah_g + (size_t)(bm + r) * K + k0 + cu * 2);
            cp16(al_s + (uint32_t)(r * 20 + cu) * 4u,
                 Al_g + (size_t)(bm + r) * K + k0 + cu * 2);
        }
#pragma unroll
        for (int p = 0; p < 2; p++) {
            int idx = tid + p * 256;           // 512 chunks per B buffer
            int kp = idx >> 5;
            int cu = (idx & 31) << 2;
            cp16(bh_s + (uint32_t)(kp * 136 + cu) * 4u,
                 Bh_g + (size_t)((k0 >> 1) + kp) * N + bn + cu);
            cp16(bl_s + (uint32_t)(kp * 136 + cu) * 4u,
                 Bl_g + (size_t)((k0 >> 1) + kp) * N + bn + cu);
        }
        CP_COMMIT();
        CP_WAIT0();
        __syncthreads();

        // ---- MMA phase (validated indexing) ----
#pragma unroll
        for (int ks = 0; ks < 2; ks++) {
            const int kb2 = ks * 8;
            uint32_t afh[4][4], afl[4][4], bfh[4][2], bfl[4][2];
#pragma unroll
            for (int mt = 0; mt < 4; mt++) {
                int r0 = wm * 64 + mt * 16;
                int i0 = (r0 + g) * 20 + kb2 + t;
                int i1 = (r0 + 8 + g) * 20 + kb2 + t;
                afh[mt][0] = Ah2[i0];     afl[mt][0] = Al2[i0];
                afh[mt][1] = Ah2[i1];     afl[mt][1] = Al2[i1];
                afh[mt][2] = Ah2[i0 + 4]; afl[mt][2] = Al2[i0 + 4];
                afh[mt][3] = Ah2[i1 + 4]; afl[mt][3] = Al2[i1 + 4];
            }
#pragma unroll
            for (int nt = 0; nt < 4; nt++) {
                int c0 = wn * 32 + nt * 8;
                int i0 = (kb2 + t) * 136 + c0 + g;
                int i1 = (kb2 + t + 4) * 136 + c0 + g;
                bfh[nt][0] = Bh2[i0]; bfl[nt][0] = Bl2[i0];
                bfh[nt][1] = Bh2[i1]; bfl[nt][1] = Bl2[i1];
            }
#pragma unroll
            for (int mt = 0; mt < 4; mt++)
#pragma unroll
                for (int nt = 0; nt < 4; nt++)
                    mma3_f16(acc[mt][nt], afh[mt], afl[mt], bfh[nt], bfl[nt]);
        }
        __syncthreads();   // buffers consumed; next iter may overwrite
    }

    // ---- epilogue ----
    if (mode == 0) {
#pragma unroll
        for (int mt = 0; mt < 4; mt++) {
            int row = bm + wm * 64 + mt * 16 + g;
#pragma unroll
            for (int nt = 0; nt < 4; nt++) {
                int col = bn + wn * 32 + nt * 8 + 2 * t;
                *reinterpret_cast<float2*>(Cf + (size_t)row * N + col) =
                    make_float2(acc[mt][nt][0], acc[mt][nt][1]);
                *reinterpret_cast<float2*>(Cf + (size_t)(row + 8) * N + col) =
                    make_float2(acc[mt][nt][2], acc[mt][nt][3]);
            }
        }
    } else {
#pragma unroll
        for (int mt = 0; mt < 4; mt++) {
            int row = bm + wm * 64 + mt * 16 + g;
#pragma unroll
            for (int nt = 0; nt < 4; nt++) {
                int col = bn + wn * 32 + nt * 8 + 2 * t;
                uint32_t hh, ll;
                f16_split2(acc[mt][nt][0], acc[mt][nt][1], hh, ll);
                *reinterpret_cast<uint32_t*>(Ch + (size_t)row * N + col) = hh;
                *reinterpret_cast<uint32_t*>(Cl + (size_t)row * N + col) = ll;
                f16_split2(acc[mt][nt][2], acc[mt][nt][3], hh, ll);
                *reinterpret_cast<uint32_t*>(Ch + (size_t)(row + 8) * N + col) = hh;
                *reinterpret_cast<uint32_t*>(Cl + (size_t)(row + 8) * N + col) = ll;
            }
        }
    }
}

// ---------------------------------------------------------------------------
// Flash attention, all inputs pre-split fp16. Block = 128 thr (4 warps), 64 q-rows.
// smem (u32): Kh2/Kl2 [64][36] (pairs along d), Vh2/Vl2 [32][72] (pairs along j,
//   built by PRMT repack), Pregion [64][36] x2 = V raw staging ∪ P operand.
// K prefetched mid-tile (after S), V prefetched after PV. Output: split fp16 ao.
// NOTE: reference MULTIPLIES logits by sqrt(64)=8.
// ---------------------------------------------------------------------------
#define FKT (64 * 36)    // 2304
#define FVT (32 * 72)    // 2304
#define FLASH_SMEM ((2 * FKT + 2 * FVT + 2 * FKT) * 4)   // 55296 bytes

__global__ void __launch_bounds__(128, 3)
flash_f16p_kernel(const __half* __restrict__ Qh_g, const __half* __restrict__ Ql_g,
                  const __half* __restrict__ KVh_g, const __half* __restrict__ KVl_g,
                  __half* __restrict__ Oh, __half* __restrict__ Ol) {
    extern __shared__ uint32_t sm[];
    uint32_t* Kh2 = sm;                 // 2304
    uint32_t* Kl2 = sm + FKT;           // 2304
    uint32_t* Vh2 = sm + 2 * FKT;       // 2304
    uint32_t* Vl2 = Vh2 + FVT;          // 2304
    uint32_t* Prh = Vh2 + 2 * FVT;      // 2304  (V raw ∪ P operand; Q staged via Vh2/Vl2)
    uint32_t* Prl = Prh + FKT;          // 2304
    const uint32_t kh_s = smem_u32(Kh2);
    const uint32_t kl_s = smem_u32(Kl2);
    const uint32_t vh_s = smem_u32(Vh2);
    const uint32_t vl_s = smem_u32(Vl2);
    const uint32_t ph_s = smem_u32(Prh);
    const uint32_t pl_s = smem_u32(Prl);

    const int tid  = threadIdx.x;
    const int lane = tid & 31;
    const int warp = tid >> 5;
    const int g = lane >> 2;
    const int t = lane & 3;
    const int wr = warp * 16;

    const int b  = blockIdx.z;
    const int h  = blockIdx.y;
    const int q0 = blockIdx.x * 64;

    const __half* Kbh = KVh_g + (size_t)b * 2048 * 2048 + h * 64;
    const __half* Kbl = KVl_g + (size_t)b * 2048 * 2048 + h * 64;

    // issue K tile loads for row j0 into Kh2/Kl2
    auto load_K = [&](int j0) {
#pragma unroll
        for (int p = 0; p < 4; p++) {
            int idx = tid + p * 128;          // 512 chunks per buffer
            int r  = idx >> 3;
            int cu = (idx & 7) << 2;
            cp16(kh_s + (uint32_t)(r * 36 + cu) * 4u, Kbh + (size_t)(j0 + r) * 2048 + cu * 2);
            cp16(kl_s + (uint32_t)(r * 36 + cu) * 4u, Kbl + (size_t)(j0 + r) * 2048 + cu * 2);
        }
    };
    // issue V tile loads for row j0 into Pregion (raw, pairs along d)
    auto load_V = [&](int j0) {
#pragma unroll
        for (int p = 0; p < 4; p++) {
            int idx = tid + p * 128;
            int r  = idx >> 3;
            int cu = (idx & 7) << 2;
            cp16(ph_s + (uint32_t)(r * 36 + cu) * 4u, Kbh + (size_t)(j0 + r) * 2048 + 1024 + cu * 2);
            cp16(pl_s + (uint32_t)(r * 36 + cu) * 4u, Kbl + (size_t)(j0 + r) * 2048 + 1024 + cu * 2);
        }
    };

    // ---- prologue: K0, V0, Q (staged via Vh2/Vl2) ----
    load_K(0); CP_COMMIT();
    load_V(0); CP_COMMIT();
    {
        const __half* Qbh = Qh_g + (size_t)(b * 2048 + q0) * 1024 + h * 64;
        const __half* Qbl = Ql_g + (size_t)(b * 2048 + q0) * 1024 + h * 64;
#pragma unroll
        for (int p = 0; p < 4; p++) {
            int idx = tid + p * 128;
            int r  = idx >> 3;
            int cu = (idx & 7) << 2;
            cp16(vh_s + (uint32_t)(r * 36 + cu) * 4u, Qbh + (size_t)r * 1024 + cu * 2);
            cp16(vl_s + (uint32_t)(r * 36 + cu) * 4u, Qbl + (size_t)r * 1024 + cu * 2);
        }
        CP_COMMIT();
    }
    CP_WAIT0();
    __syncthreads();

    uint32_t qh[4][4], ql[4][4];
#pragma unroll
    for (int ks = 0; ks < 4; ks++) {
        int kb = ks * 8;
        int i0 = (wr + g) * 36 + kb + t;
        int i1 = (wr + 8 + g) * 36 + kb + t;
        qh[ks][0] = Vh2[i0];     ql[ks][0] = Vl2[i0];
        qh[ks][1] = Vh2[i1];     ql[ks][1] = Vl2[i1];
        qh[ks][2] = Vh2[i0 + 4]; ql[ks][2] = Vl2[i0 + 4];
        qh[ks][3] = Vh2[i1 + 4]; ql[ks][3] = Vl2[i1 + 4];
    }
    __syncthreads();   // Vh2/Vl2 free for V repack

    float of[8][4];
#pragma unroll
    for (int i = 0; i < 8; i++)
#pragma unroll
        for (int v = 0; v < 4; v++) of[i][v] = 0.f;
    float m0 = -1e30f, m1 = -1e30f, l0 = 0.f, l1 = 0.f;

    for (int it = 0; it < 32; it++) {
        CP_WAIT0();          // K(it) and V(it) complete
        __syncthreads();

        // ---- repack V raw (Pregion, pairs along d) -> Vh2/Vl2 (pairs along j) ----
        // FIXED (round 13): 1024 tasks — jp in 0..31, dp in 0..31 (was dp 0..15,
        // leaving d-columns 32..63 uninitialized -> NaN).
#pragma unroll
        for (int p = 0; p < 8; p++) {
            int idx = tid + p * 128;         // 1024 (jp,dp) tasks
            int jp = idx >> 5;               // 0..31
            int dp = idx & 31;               // 0..31
            uint32_t X = Prh[(2 * jp) * 36 + dp];
            uint32_t Y = Prh[(2 * jp + 1) * 36 + dp];
            Vh2[jp * 72 + 2 * dp]     = __byte_perm(X, Y, 0x5410);
            Vh2[jp * 72 + 2 * dp + 1] = __byte_perm(X, Y, 0x7632);
            X = Prl[(2 * jp) * 36 + dp];
            Y = Prl[(2 * jp + 1) * 36 + dp];
            Vl2[jp * 72 + 2 * dp]     = __byte_perm(X, Y, 0x5410);
            Vl2[jp * 72 + 2 * dp + 1] = __byte_perm(X, Y, 0x7632);
        }
        __syncthreads();     // Vh2 ready; Pregion free

        // ---- S = Q K^T ----
        float sf[8][4];
#pragma unroll
        for (int nt = 0; nt < 8; nt++)
#pragma unroll
            for (int v = 0; v < 4; v++) sf[nt][v] = 0.f;
#pragma unroll
        for (int ks = 0; ks < 4; ks++) {
            int kb2 = ks * 8;
#pragma unroll
            for (int nt = 0; nt < 8; nt++) {
                int i0 = (nt * 8 + g) * 36 + kb2 + t;
                uint32_t bh[2] = { Kh2[i0], Kh2[i0 + 4] };
                uint32_t bl[2] = { Kl2[i0], Kl2[i0 + 4] };
                mma3_f16(sf[nt], qh[ks], ql[ks], bh, bl);
            }
        }
        __syncthreads();     // all warps done reading K
        if (it + 1 < 32) load_K((it + 1) * 64);   // prefetch next K
        CP_COMMIT();

        // ---- online softmax (x8 scale; rows g and g+8) ----
        float r0m = -1e30f, r1m = -1e30f;
#pragma unroll
        for (int nt = 0; nt < 8; nt++) {
            sf[nt][0] *= 8.f; sf[nt][1] *= 8.f; sf[nt][2] *= 8.f; sf[nt][3] *= 8.f;
            r0m = fmaxf(r0m, fmaxf(sf[nt][0], sf[nt][1]));
            r1m = fmaxf(r1m, fmaxf(sf[nt][2], sf[nt][3]));
        }
        r0m = fmaxf(r0m, __shfl_xor_sync(0xffffffffu, r0m, 1));
        r0m = fmaxf(r0m, __shfl_xor_sync(0xffffffffu, r0m, 2));
        r1m = fmaxf(r1m, __shfl_xor_sync(0xffffffffu, r1m, 1));
        r1m = fmaxf(r1m, __shfl_xor_sync(0xffffffffu, r1m, 2));

        float mn0 = fmaxf(m0, r0m), mn1 = fmaxf(m1, r1m);
        float cr0 = __expf(m0 - mn0), cr1 = __expf(m1 - mn1);
        float s0 = 0.f, s1 = 0.f;
#pragma unroll
        for (int nt = 0; nt < 8; nt++) {
            sf[nt][0] = __expf(sf[nt][0] - mn0);
            sf[nt][1] = __expf(sf[nt][1] - mn0);
            sf[nt][2] = __expf(sf[nt][2] - mn1);
            sf[nt][3] = __expf(sf[nt][3] - mn1);
            s0 += sf[nt][0] + sf[nt][1];
            s1 += sf[nt][2] + sf[nt][3];
        }
        s0 += __shfl_xor_sync(0xffffffffu, s0, 1);
        s0 += __shfl_xor_sync(0xffffffffu, s0, 2);
        s1 += __shfl_xor_sync(0xffffffffu, s1, 1);
        s1 += __shfl_xor_sync(0xffffffffu, s1, 2);
        l0 = l0 * cr0 + s0;  m0 = mn0;
        l1 = l1 * cr1 + s1;  m1 = mn1;
#pragma unroll
        for (int dt = 0; dt < 8; dt++) {
            of[dt][0] *= cr0; of[dt][1] *= cr0;
            of[dt][2] *= cr1; of[dt][3] *= cr1;
        }

        // ---- stage P fp16 hi/lo into Pregion (per-warp-private rows) ----
#pragma unroll
        for (int nt = 0; nt < 8; nt++) {
            uint32_t hh, ll;
            f16_split2(sf[nt][0], sf[nt][1], hh, ll);
            Prh[(wr + g) * 36 + nt * 4 + t] = hh;
            Prl[(wr + g) * 36 + nt * 4 + t] = ll;
            f16_split2(sf[nt][2], sf[nt][3], hh, ll);
            Prh[(wr + 8 + g) * 36 + nt * 4 + t] = hh;
            Prl[(wr + 8 + g) * 36 + nt * 4 + t] = ll;
        }
        __syncwarp();

        // ---- O += P V ----
#pragma unroll
        for (int ks = 0; ks < 4; ks++) {
            int kb2 = ks * 8;
            int i0 = (wr + g) * 36 + kb2 + t;
            int i1 = (wr + 8 + g) * 36 + kb2 + t;
            uint32_t ah[4] = { Prh[i0], Prh[i1], Prh[i0 + 4], Prh[i1 + 4] };
            uint32_t al[4] = { Prl[i0], Prl[i1], Prl[i0 + 4], Prl[i1 + 4] };
#pragma unroll
            for (int nt = 0; nt < 8; nt++) {
                int j0i = (kb2 + t) * 72 + nt * 8 + g;
                int j1i = (kb2 + t + 4) * 72 + nt * 8 + g;
                uint32_t bh[2] = { Vh2[j0i], Vh2[j1i] };
                uint32_t bl[2] = { Vl2[j0i], Vl2[j1i] };
                mma3_f16(of[nt], ah, al, bh, bl);
            }
        }
        __syncthreads();     // all warps done with Pregion + Vh2
        if (it + 1 < 32) load_V((it + 1) * 64);   // prefetch next V into Pregion
        CP_COMMIT();
    }

    // ---- epilogue: split-fp16 ao ----
    float inv0 = 1.f / l0, inv1 = 1.f / l1;
    int row0 = b * 2048 + q0 + wr + g;
#pragma unroll
    for (int nt = 0; nt < 8; nt++) {
        int col = h * 64 + nt * 8 + 2 * t;
        uint32_t hh, ll;
        f16_split2(of[nt][0] * inv0, of[nt][1] * inv0, hh, ll);
        *reinterpret_cast<uint32_t*>(Oh + (size_t)row0 * 1024 + col) = hh;
        *reinterpret_cast<uint32_t*>(Ol + (size_t)row0 * 1024 + col) = ll;
        f16_split2(of[nt][2] * inv1, of[nt][3] * inv1, hh, ll);
        *reinterpret_cast<uint32_t*>(Oh + (size_t)(row0 + 8) * 1024 + col) = hh;
        *reinterpret_cast<uint32_t*>(Ol + (size_t)(row0 + 8) * 1024 + col) = ll;
    }
}

// ---------------------------------------------------------------------------
extern "C" void kernel_launch(void* const* d_in, const int* in_sizes, int n_in,
                              void* d_out, int out_size) {
    const float* x     = (const float*)d_in[0];   // [2,2048,1024]
    const float* w_q   = (const float*)d_in[1];   // [1024,1024]
    const float* w_vk  = (const float*)d_in[2];   // [1024,2048]
    const float* w_out = (const float*)d_in[3];   // [1024,1024]
    float* out = (float*)d_out;                   // [2,2048,1024]

    __half *xh, *xl, *qh, *ql, *kvh, *kvl, *aoh, *aol;
    uint32_t *wqh, *wql, *wvkh, *wvkl, *woh, *wol;
    cudaGetSymbolAddress((void**)&xh,  g_xh);   cudaGetSymbolAddress((void**)&xl,  g_xl);
    cudaGetSymbolAddress((void**)&wqh, g_wq_h); cudaGetSymbolAddress((void**)&wql, g_wq_l);
    cudaGetSymbolAddress((void**)&wvkh, g_wvk_h); cudaGetSymbolAddress((void**)&wvkl, g_wvk_l);
    cudaGetSymbolAddress((void**)&woh, g_wo_h); cudaGetSymbolAddress((void**)&wol, g_wo_l);
    cudaGetSymbolAddress((void**)&qh,  g_qh);   cudaGetSymbolAddress((void**)&ql,  g_ql);
    cudaGetSymbolAddress((void**)&kvh, g_kvh);  cudaGetSymbolAddress((void**)&kvl, g_kvl);
    cudaGetSymbolAddress((void**)&aoh, g_aoh);  cudaGetSymbolAddress((void**)&aol, g_aol);

    cudaFuncSetAttribute(flash_f16p_kernel,
                         cudaFuncAttributeMaxDynamicSharedMemorySize, FLASH_SMEM);

    // presplit (once per launch; cheap)
    presplit_plain<<<4096, 256>>>(x, xh, xl, 4096 * 1024);
    presplit_wpair<<<512,  256>>>(w_q,   wqh,  wql,  1024, 1024);
    presplit_wpair<<<1024, 256>>>(w_vk,  wvkh, wvkl, 1024, 2048);
    presplit_wpair<<<512,  256>>>(w_out, woh,  wol,  1024, 1024);

    // Q = x @ w_q  -> split fp16
    gemm_f16p_kernel<<<dim3(8, 32), 256>>>(xh, xl, wqh, wql,
                                           nullptr, qh, ql, 4096, 1024, 1024, 1);
    // KV = x @ w_vk -> split fp16
    gemm_f16p_kernel<<<dim3(16, 32), 256>>>(xh, xl, wvkh, wvkl,
                                            nullptr, kvh, kvl, 4096, 2048, 1024, 1);
    // attention -> split fp16 ao
    flash_f16p_kernel<<<dim3(32, 16, 2), 128, FLASH_SMEM>>>(qh, ql, kvh, kvl, aoh, aol);
    // out = ao @ w_out -> fp32
    gemm_f16p_kernel<<<dim3(8, 32), 256>>>(aoh, aol, woh, wol,
                                           out, nullptr, nullptr, 4096, 1024, 1024, 0);
}